// round 6
// baseline (speedup 1.0000x reference)
#include <cuda_runtime.h>
#include <cstdint>

#define CTOT  512
#define BG    256      // N*G = 32*8 groups
#define CGH   32       // channels per half-group
#define PLANE 4096     // 64*64

#define NK1   16384    // K1-role blocks (BG * 64)
#define NK3   8192     // K3-role blocks (BG * 32)

// scratch (device globals: no allocation allowed)
__device__ float g_xh[BG * CGH * 64];   // row means of x1
__device__ float g_xw[BG * CGH * 64];   // col means of x1
__device__ float g_xs[BG * CGH];        // plane means of x1
__device__ float g_ah[BG * CGH * 64];   // conv_h output
__device__ float g_aw[BG * CGH * 64];   // conv_w output
__device__ int   g_sync[2 * BG];        // [0..255] counters, [256..511] flags

__device__ __forceinline__ float sigmoid_exact(float z) {
    return __fdividef(1.0f, 1.0f + __expf(-z));
}
// 1-MUFU sigmoid: sigmoid(z) = 0.5*tanh(z/2) + 0.5
__device__ __forceinline__ float sigmoid_fast(float z) {
    float t;
    asm("tanh.approx.f32 %0, %1;" : "=f"(t) : "f"(z * 0.5f));
    return fmaf(0.5f, t, 0.5f);
}

struct K1Smem {
    float4 cp4[256];
    float  part[2];
    float  ws[8];
    float  sgate;
    int    elect;
};
struct K2Smem {
    float ybuf[32][128];     // inputs, then conv1 output (reused)
    float wbuf[2048];        // phase A: w1 ; phase B: wh | ww
    float b1[32], bh[32], bw[32], gg[32], gb[32];
    float mu[32], rs[32];
};
union USmem { K1Smem k1; K2Smem k2; };

// ---------------------------------------------------------------------------
__global__ __launch_bounds__(256, 7) void fused_kernel(
    const float* __restrict__ x,
    const float* __restrict__ cweight, const float* __restrict__ cbias,
    const float* __restrict__ w1,  const float* __restrict__ b1,
    const float* __restrict__ gng, const float* __restrict__ gnb,
    const float* __restrict__ wh,  const float* __restrict__ bh,
    const float* __restrict__ wwv, const float* __restrict__ bw,
    float* __restrict__ out)
{
    __shared__ USmem sm;
    const int bid = blockIdx.x;
    const int t   = threadIdx.x;

    if (bid < NK1) {
        // =================== K1 roles ===================
        const int cc = bid & 63;         // 0..63
        const int bg = bid >> 6;         // 0..255
        const int n  = bg >> 3;
        const int g  = bg & 7;

        const float4* p4 = (const float4*)(x + (size_t)(n * CTOT + g * 64 + cc) * PLANE);
        float4 v[4];
        #pragma unroll
        for (int i = 0; i < 4; i++) v[i] = p4[t + 256 * i];

        if (cc < CGH) {
            // ----- channel branch (x0): read, reduce, gate, write -----
            float s = 0.f;
            #pragma unroll
            for (int i = 0; i < 4; i++) s += v[i].x + v[i].y + v[i].z + v[i].w;
            #pragma unroll
            for (int o = 16; o > 0; o >>= 1) s += __shfl_xor_sync(0xffffffffu, s, o);
            if ((t & 31) == 0) sm.k1.ws[t >> 5] = s;
            __syncthreads();
            if (t == 0) {
                float tot = 0.f;
                #pragma unroll
                for (int i = 0; i < 8; i++) tot += sm.k1.ws[i];
                float gap = tot * (1.0f / 4096.0f);
                sm.k1.sgate = sigmoid_exact(cweight[cc] * gap + cbias[cc]);
            }
            __syncthreads();
            const float gate = sm.k1.sgate;

            const int c_prev  = g * 64 + cc;
            const int c_final = 2 * (c_prev & 255) + (c_prev >> 8);
            float4* o4 = (float4*)(out + (size_t)(n * CTOT + c_final) * PLANE);
            #pragma unroll
            for (int i = 0; i < 4; i++) {
                float4 r = v[i];
                r.x *= gate; r.y *= gate; r.z *= gate; r.w *= gate;
                o4[t + 256 * i] = r;
            }
            return;
        }

        // ----- spatial branch (x1) reductions -----
        const int c1   = cc - CGH;
        const int base = (bg * CGH + c1) * 64;

        #pragma unroll
        for (int i = 0; i < 4; i++) {
            float s = v[i].x + v[i].y + v[i].z + v[i].w;
            #pragma unroll
            for (int o = 8; o > 0; o >>= 1) s += __shfl_xor_sync(0xffffffffu, s, o);
            if ((t & 15) == 0)
                g_xh[base + (t >> 4) + 16 * i] = s * (1.0f / 64.0f);
        }

        float4 acc;
        acc.x = v[0].x + v[1].x + v[2].x + v[3].x;
        acc.y = v[0].y + v[1].y + v[2].y + v[3].y;
        acc.z = v[0].z + v[1].z + v[2].z + v[3].z;
        acc.w = v[0].w + v[1].w + v[2].w + v[3].w;

        sm.k1.cp4[t] = acc;
        __syncthreads();

        if (t < 64) {
            const int grp = t >> 2, comp = t & 3;
            const float* cpf = (const float*)sm.k1.cp4;
            float cs = 0.f;
            #pragma unroll
            for (int k = 0; k < 16; k++)
                cs += cpf[(k * 16 + grp) * 4 + comp];
            g_xw[base + t] = cs * (1.0f / 64.0f);

            float s2 = cs;
            #pragma unroll
            for (int o = 16; o > 0; o >>= 1) s2 += __shfl_xor_sync(0xffffffffu, s2, o);
            if ((t & 31) == 0) sm.k1.part[t >> 5] = s2;
        }
        __syncthreads();
        if (t == 0)
            g_xs[bg * CGH + c1] = (sm.k1.part[0] + sm.k1.part[1]) * (1.0f / 4096.0f);

        // ----- elect last block of this bg to run the K2 epilogue -----
        __threadfence();
        __syncthreads();
        if (t == 0)
            sm.k1.elect = (atomicAdd(&g_sync[bg], 1) == CGH - 1);
        __syncthreads();
        if (!sm.k1.elect) return;
        __syncthreads();                 // everyone read 'elect'; safe to reuse union

        // =================== K2 epilogue (one block per bg) ===================
        {
            K2Smem& k2 = sm.k2;
            const int p  = t & 127;          // position 0..127
            const int oh = (t >> 7) * 16;    // output-channel half base

            // phase A: w1 weights + all small vectors
            #pragma unroll
            for (int j = 0; j < 4; j++) k2.wbuf[t + 256 * j] = w1[t + 256 * j];
            if (t < 32) {
                k2.b1[t] = b1[t];  k2.bh[t] = bh[t];  k2.bw[t] = bw[t];
                k2.gg[t] = gng[t]; k2.gb[t] = gnb[t];
            }
            // inputs into ybuf[k][p] (cross-block data -> L2 loads)
            #pragma unroll
            for (int j = 0; j < 16; j++) {
                const int idx = t + 256 * j;
                const int k   = idx >> 7;
                const int pp  = idx & 127;
                const int src = (bg * CGH + k) * 64;
                k2.ybuf[k][pp] = (pp < 64) ? __ldcg(&g_xh[src + pp])
                                           : __ldcg(&g_xw[src + pp - 64]);
            }
            __syncthreads();

            // conv1: thread owns (p, oh..oh+15)
            float a1[16];
            #pragma unroll
            for (int o = 0; o < 16; o++) a1[o] = k2.b1[oh + o];
            #pragma unroll
            for (int i = 0; i < 32; i++) {
                const float ci = k2.ybuf[i][p];
                #pragma unroll
                for (int o = 0; o < 16; o++)
                    a1[o] += k2.wbuf[(oh + o) * 32 + i] * ci;
            }
            __syncthreads();                 // all ybuf reads done
            #pragma unroll
            for (int o = 0; o < 16; o++) k2.ybuf[oh + o][p] = a1[o];
            __syncthreads();

            // GroupNorm stats: warp w handles channels w*4..w*4+3
            {
                const int w = t >> 5, l = t & 31;
                #pragma unroll
                for (int j = 0; j < 4; j++) {
                    const int o = w * 4 + j;
                    float e0 = k2.ybuf[o][l],      e1 = k2.ybuf[o][l + 32],
                          e2 = k2.ybuf[o][l + 64], e3 = k2.ybuf[o][l + 96];
                    float s  = e0 + e1 + e2 + e3;
                    float ss = e0 * e0 + e1 * e1 + e2 * e2 + e3 * e3;
                    #pragma unroll
                    for (int off = 16; off > 0; off >>= 1) {
                        s  += __shfl_xor_sync(0xffffffffu, s, off);
                        ss += __shfl_xor_sync(0xffffffffu, ss, off);
                    }
                    if (l == 0) {
                        float m  = s * (1.0f / 128.0f);
                        float vv = ss * (1.0f / 128.0f) - m * m;
                        k2.mu[o] = m;
                        k2.rs[o] = rsqrtf(vv + 1e-5f);
                    }
                }
            }
            __syncthreads();

            // normalize + affine + h-swish in place
            #pragma unroll
            for (int j = 0; j < 16; j++) {
                const int k = oh + j;
                float vv = (k2.ybuf[k][p] - k2.mu[k]) * k2.rs[k] * k2.gg[k] + k2.gb[k];
                float hs = fminf(fmaxf(vv + 3.0f, 0.0f), 6.0f) * (1.0f / 6.0f);
                k2.ybuf[k][p] = vv * hs;
            }
            __syncthreads();

            // phase B: wh | ww weights
            #pragma unroll
            for (int j = 0; j < 4; j++) {
                k2.wbuf[t + 256 * j]        = wh[t + 256 * j];
                k2.wbuf[1024 + t + 256 * j] = wwv[t + 256 * j];
            }
            __syncthreads();

            // convh (p<64) / convw (p>=64): outputs oh..oh+15 at position p
            {
                const int half = p >> 6;
                const int r    = p & 63;
                const float* wsel = k2.wbuf + (half ? 1024 : 0);
                const float* bsel = half ? k2.bw : k2.bh;
                float a2[16];
                #pragma unroll
                for (int o = 0; o < 16; o++) a2[o] = bsel[oh + o];
                #pragma unroll
                for (int i = 0; i < 32; i++) {
                    const float ci = k2.ybuf[i][p];
                    #pragma unroll
                    for (int o = 0; o < 16; o++)
                        a2[o] += wsel[(oh + o) * 32 + i] * ci;
                }
                float* dst = half ? g_aw : g_ah;
                #pragma unroll
                for (int o = 0; o < 16; o++)
                    dst[(bg * CGH + oh + o) * 64 + r] = a2[o];
            }

            // publish: release flag for this bg
            __threadfence();
            __syncthreads();
            if (t == 0)
                ((volatile int*)g_sync)[BG + bg] = 1;
        }
    } else {
        // =================== K3 role: spatial gating ===================
        const int k  = bid - NK1;
        const int bg = k >> 5;           // ascending with bid -> flags set in order
        const int c1 = k & 31;
        const int n  = bg >> 3;
        const int g  = bg & 7;

        // prefetch x1 plane (in flight during spin)
        const float4* p4 = (const float4*)(x + (size_t)(n * CTOT + g * 64 + 32 + c1) * PLANE);
        float4 v[4];
        #pragma unroll
        for (int i = 0; i < 4; i++) v[i] = p4[t + 256 * i];

        // wait for this bg's epilogue (bid order makes this near-zero spin)
        if (t == 0) {
            while (((volatile int*)g_sync)[BG + bg] == 0) { }
        }
        __syncthreads();

        const int base = (bg * CGH + c1) * 64;
        const float  xs  = __ldcg(&g_xs[bg * CGH + c1]);
        const float4 aw4 = __ldcg((const float4*)g_aw + (base >> 2) + (t & 15));
        float ah[4];
        #pragma unroll
        for (int i = 0; i < 4; i++)
            ah[i] = __ldcg(&g_ah[base + (t >> 4) + 16 * i]) * xs;

        const int c_prev  = g * 64 + 32 + c1;
        const int c_final = 2 * (c_prev & 255) + (c_prev >> 8);
        float4* o4 = (float4*)(out + (size_t)(n * CTOT + c_final) * PLANE);

        #pragma unroll
        for (int i = 0; i < 4; i++) {
            float4 r = v[i];
            r.x *= sigmoid_fast(ah[i] * aw4.x);
            r.y *= sigmoid_fast(ah[i] * aw4.y);
            r.z *= sigmoid_fast(ah[i] * aw4.z);
            r.w *= sigmoid_fast(ah[i] * aw4.w);
            o4[t + 256 * i] = r;
        }
    }
}

// ---------------------------------------------------------------------------
extern "C" void kernel_launch(void* const* d_in, const int* in_sizes, int n_in,
                              void* d_out, int out_size)
{
    const float* x       = (const float*)d_in[0];
    const float* cweight = (const float*)d_in[1];
    const float* cbias   = (const float*)d_in[2];
    const float* conv1_w = (const float*)d_in[3];
    const float* conv1_b = (const float*)d_in[4];
    const float* gn_g    = (const float*)d_in[5];
    const float* gn_b    = (const float*)d_in[6];
    const float* convh_w = (const float*)d_in[7];
    const float* convh_b = (const float*)d_in[8];
    const float* convw_w = (const float*)d_in[9];
    const float* convw_b = (const float*)d_in[10];
    float* out = (float*)d_out;

    // reset per-bg counters/flags (graph replay safe; captured as memset node)
    void* sync_ptr = nullptr;
    cudaGetSymbolAddress(&sync_ptr, g_sync);
    cudaMemsetAsync(sync_ptr, 0, 2 * BG * sizeof(int), 0);

    fused_kernel<<<NK1 + NK3, 256>>>(
        x, cweight, cbias,
        conv1_w, conv1_b, gn_g, gn_b,
        convh_w, convh_b, convw_w, convw_b,
        out);
}

// round 7
// speedup vs baseline: 2.1020x; 2.1020x over previous
#include <cuda_runtime.h>
#include <cstdint>

#define CTOT  512
#define BG    256      // N*G = 32*8 groups
#define CGH   32       // channels per half-group
#define PLANE 4096     // 64*64

// scratch (device globals: no allocation allowed)
__device__ float g_xh[BG * CGH * 64];   // row means of x1
__device__ float g_xw[BG * CGH * 64];   // col means of x1
__device__ float g_xs[BG * CGH];        // plane means of x1
__device__ float g_ah[BG * CGH * 64];   // conv_h output
__device__ float g_aw[BG * CGH * 64];   // conv_w output

__device__ __forceinline__ float sigmoid_exact(float z) {
    return __fdividef(1.0f, 1.0f + __expf(-z));
}
// 1-MUFU sigmoid: sigmoid(z) = 0.5*tanh(z/2) + 0.5
__device__ __forceinline__ float sigmoid_fast(float z) {
    float t;
    asm("tanh.approx.f32 %0, %1;" : "=f"(t) : "f"(z * 0.5f));
    return fmaf(0.5f, t, 0.5f);
}

// ---------------------------------------------------------------------------
// K1a: x1 reductions only (row/col/total means). One block per (bg, c1).
// Critical-path producer for K2 — runs first, nothing else in the way.
// ---------------------------------------------------------------------------
__global__ __launch_bounds__(256) void k1a_kernel(const float* __restrict__ x)
{
    const int c1 = blockIdx.x;          // 0..31
    const int bg = blockIdx.y;          // 0..255
    const int n  = bg >> 3;
    const int g  = bg & 7;
    const int t  = threadIdx.x;

    const float4* p4 = (const float4*)(x + (size_t)(n * CTOT + g * 64 + 32 + c1) * PLANE);
    float4 v[4];
    #pragma unroll
    for (int i = 0; i < 4; i++) v[i] = __ldcs(&p4[t + 256 * i]);

    const int base = (bg * CGH + c1) * 64;

    // row sums: reduce over 16-lane groups sharing t>>4
    #pragma unroll
    for (int i = 0; i < 4; i++) {
        float s = v[i].x + v[i].y + v[i].z + v[i].w;
        #pragma unroll
        for (int o = 8; o > 0; o >>= 1) s += __shfl_xor_sync(0xffffffffu, s, o);
        if ((t & 15) == 0)
            g_xh[base + (t >> 4) + 16 * i] = s * (1.0f / 64.0f);
    }

    // column partials
    float4 acc;
    acc.x = v[0].x + v[1].x + v[2].x + v[3].x;
    acc.y = v[0].y + v[1].y + v[2].y + v[3].y;
    acc.z = v[0].z + v[1].z + v[2].z + v[3].z;
    acc.w = v[0].w + v[1].w + v[2].w + v[3].w;

    __shared__ float4 cp4[256];
    __shared__ float part[2];
    cp4[t] = acc;
    __syncthreads();

    if (t < 64) {
        const int grp = t >> 2, comp = t & 3;
        const float* cpf = (const float*)cp4;
        float cs = 0.f;
        #pragma unroll
        for (int k = 0; k < 16; k++)
            cs += cpf[(k * 16 + grp) * 4 + comp];
        g_xw[base + t] = cs * (1.0f / 64.0f);

        float s2 = cs;
        #pragma unroll
        for (int o = 16; o > 0; o >>= 1) s2 += __shfl_xor_sync(0xffffffffu, s2, o);
        if ((t & 31) == 0) part[t >> 5] = s2;
    }
    __syncthreads();
    if (t == 0)
        g_xs[bg * CGH + c1] = (part[0] + part[1]) * (1.0f / 4096.0f);
}

// ---------------------------------------------------------------------------
// K2: conv1x1 -> GroupNorm -> h-swish -> convh/convw. One 256-thread block
// per bg. PDL on K1a; triggers PLC after prologue so K3 pre-launches.
// ---------------------------------------------------------------------------
__global__ __launch_bounds__(256) void k2_kernel(
    const float* __restrict__ w1, const float* __restrict__ b1,
    const float* __restrict__ gng, const float* __restrict__ gnb,
    const float* __restrict__ wh, const float* __restrict__ bh,
    const float* __restrict__ wwv, const float* __restrict__ bw)
{
    const int bg = blockIdx.x;     // 0..255
    const int t  = threadIdx.x;    // 0..255
    const int p  = t & 127;        // position 0..127
    const int oh = (t >> 7) * 16;  // output-channel half base: 0 or 16

    __shared__ float yin[32][128];
    __shared__ float ybuf[32][128];
    __shared__ float w1s[1024], whs[1024], wws[1024];
    __shared__ float b1s[32], bhs[32], bws[32], gngs[32], gnbs[32];
    __shared__ float mus[32], rstds[32];

    // independent prologue: weights (do not depend on K1a)
    #pragma unroll
    for (int j = 0; j < 4; j++) {
        w1s[t + 256 * j] = w1[t + 256 * j];
        whs[t + 256 * j] = wh[t + 256 * j];
        wws[t + 256 * j] = wwv[t + 256 * j];
    }
    if (t < 32) {
        b1s[t] = b1[t]; bhs[t] = bh[t]; bws[t] = bw[t];
        gngs[t] = gng[t]; gnbs[t] = gnb[t];
    }
    cudaTriggerProgrammaticLaunchCompletion();   // let K3 pre-launch

    cudaGridDependencySynchronize();   // wait for K1a's g_xh/g_xw

    if (t < 128) {
        #pragma unroll
        for (int k = 0; k < 32; k++) {
            const int src = (bg * CGH + k) * 64;
            yin[k][p] = (p < 64) ? g_xh[src + p] : g_xw[src + p - 64];
        }
    }
    __syncthreads();

    // conv1: thread owns position p, outputs oh..oh+15
    {
        float c[32], acc[16];
        #pragma unroll
        for (int i = 0; i < 32; i++) c[i] = yin[i][p];
        #pragma unroll
        for (int o = 0; o < 16; o++) acc[o] = b1s[oh + o];
        #pragma unroll
        for (int i = 0; i < 32; i++) {
            const float ci = c[i];
            #pragma unroll
            for (int o = 0; o < 16; o++) acc[o] += w1s[(oh + o) * 32 + i] * ci;
        }
        #pragma unroll
        for (int o = 0; o < 16; o++) ybuf[oh + o][p] = acc[o];
    }
    __syncthreads();

    // GroupNorm stats: warp w handles channels w*4 .. w*4+3
    {
        const int w = t >> 5, l = t & 31;
        #pragma unroll
        for (int j = 0; j < 4; j++) {
            const int o = w * 4 + j;
            float e0 = ybuf[o][l], e1 = ybuf[o][l + 32],
                  e2 = ybuf[o][l + 64], e3 = ybuf[o][l + 96];
            float s  = e0 + e1 + e2 + e3;
            float ss = e0 * e0 + e1 * e1 + e2 * e2 + e3 * e3;
            #pragma unroll
            for (int off = 16; off > 0; off >>= 1) {
                s  += __shfl_xor_sync(0xffffffffu, s, off);
                ss += __shfl_xor_sync(0xffffffffu, ss, off);
            }
            if (l == 0) {
                float mu  = s * (1.0f / 128.0f);
                float var = ss * (1.0f / 128.0f) - mu * mu;
                mus[o] = mu;
                rstds[o] = rsqrtf(var + 1e-5f);
            }
        }
    }
    __syncthreads();

    // normalize + affine + h-swish
    #pragma unroll
    for (int j = 0; j < 16; j++) {
        const int k = oh + j;
        float v = (ybuf[k][p] - mus[k]) * rstds[k] * gngs[k] + gnbs[k];
        float hs = fminf(fmaxf(v + 3.0f, 0.0f), 6.0f) * (1.0f / 6.0f);
        ybuf[k][p] = v * hs;
    }
    __syncthreads();

    // convh (p<64) / convw (p>=64): outputs oh..oh+15 at position p
    {
        const int half = p >> 6;
        const int r = p & 63;
        const float* wsel = half ? wws : whs;
        const float* bsel = half ? bws : bhs;
        float c[32], acc[16];
        #pragma unroll
        for (int i = 0; i < 32; i++) c[i] = ybuf[i][p];
        #pragma unroll
        for (int o = 0; o < 16; o++) acc[o] = bsel[oh + o];
        #pragma unroll
        for (int i = 0; i < 32; i++) {
            const float ci = c[i];
            #pragma unroll
            for (int o = 0; o < 16; o++) acc[o] += wsel[(oh + o) * 32 + i] * ci;
        }
        float* dst = half ? g_aw : g_ah;
        #pragma unroll
        for (int o = 0; o < 16; o++)
            dst[(bg * CGH + oh + o) * 64 + r] = acc[o];
    }
}

// ---------------------------------------------------------------------------
// K3: spatial gating. PDL on K2; prefetch before grid-sync; triggers PLC
// immediately so K1b floods in behind it.
// ---------------------------------------------------------------------------
__global__ __launch_bounds__(256) void k3_kernel(
    const float* __restrict__ x,
    float* __restrict__ out)
{
    const int c1 = blockIdx.x;          // 0..31
    const int bg = blockIdx.y;          // 0..255
    const int n  = bg >> 3;
    const int g  = bg & 7;
    const int t  = threadIdx.x;

    cudaTriggerProgrammaticLaunchCompletion();   // let K1b launch

    // independent prologue: x1 plane prefetch
    const float4* p4 = (const float4*)(x + (size_t)(n * CTOT + g * 64 + 32 + c1) * PLANE);
    float4 v[4];
    #pragma unroll
    for (int i = 0; i < 4; i++) v[i] = __ldcs(&p4[t + 256 * i]);

    cudaGridDependencySynchronize();    // wait for K2's g_ah/g_aw/g_xs

    const int base = (bg * CGH + c1) * 64;
    const float  xs  = __ldg(&g_xs[bg * CGH + c1]);
    const float4 aw4 = __ldg((const float4*)g_aw + (base >> 2) + (t & 15));
    float ah[4];
    #pragma unroll
    for (int i = 0; i < 4; i++)
        ah[i] = __ldg(&g_ah[base + (t >> 4) + 16 * i]) * xs;

    const int c_prev  = g * 64 + 32 + c1;
    const int c_final = 2 * (c_prev & 255) + (c_prev >> 8);
    float4* o4 = (float4*)(out + (size_t)(n * CTOT + c_final) * PLANE);

    #pragma unroll
    for (int i = 0; i < 4; i++) {
        float4 r = v[i];
        r.x *= sigmoid_fast(ah[i] * aw4.x);
        r.y *= sigmoid_fast(ah[i] * aw4.y);
        r.z *= sigmoid_fast(ah[i] * aw4.z);
        r.w *= sigmoid_fast(ah[i] * aw4.w);
        __stcs(&o4[t + 256 * i], r);
    }
}

// ---------------------------------------------------------------------------
// K1b: x0 channel-gating stream. NO data dependencies on anything — launched
// last with PDL so its blocks backfill idle slots during K3.
// ---------------------------------------------------------------------------
__global__ __launch_bounds__(256) void k1b_kernel(
    const float* __restrict__ x,
    const float* __restrict__ cweight,
    const float* __restrict__ cbias,
    float* __restrict__ out)
{
    const int cc = blockIdx.x;          // 0..31
    const int bg = blockIdx.y;          // 0..255
    const int n  = bg >> 3;
    const int g  = bg & 7;
    const int t  = threadIdx.x;

    const float4* p4 = (const float4*)(x + (size_t)(n * CTOT + g * 64 + cc) * PLANE);
    float4 v[4];
    #pragma unroll
    for (int i = 0; i < 4; i++) v[i] = __ldcs(&p4[t + 256 * i]);

    float s = 0.f;
    #pragma unroll
    for (int i = 0; i < 4; i++) s += v[i].x + v[i].y + v[i].z + v[i].w;
    __shared__ float ws[8];
    __shared__ float sgate;
    #pragma unroll
    for (int o = 16; o > 0; o >>= 1) s += __shfl_xor_sync(0xffffffffu, s, o);
    if ((t & 31) == 0) ws[t >> 5] = s;
    __syncthreads();
    if (t == 0) {
        float tot = 0.f;
        #pragma unroll
        for (int i = 0; i < 8; i++) tot += ws[i];
        float gap = tot * (1.0f / 4096.0f);
        sgate = sigmoid_exact(cweight[cc] * gap + cbias[cc]);
    }
    __syncthreads();
    const float gate = sgate;

    const int c_prev  = g * 64 + cc;
    const int c_final = 2 * (c_prev & 255) + (c_prev >> 8);
    float4* o4 = (float4*)(out + (size_t)(n * CTOT + c_final) * PLANE);
    #pragma unroll
    for (int i = 0; i < 4; i++) {
        float4 r = v[i];
        r.x *= gate; r.y *= gate; r.z *= gate; r.w *= gate;
        __stcs(&o4[t + 256 * i], r);
    }
}

// ---------------------------------------------------------------------------
extern "C" void kernel_launch(void* const* d_in, const int* in_sizes, int n_in,
                              void* d_out, int out_size)
{
    const float* x       = (const float*)d_in[0];
    const float* cweight = (const float*)d_in[1];
    const float* cbias   = (const float*)d_in[2];
    const float* conv1_w = (const float*)d_in[3];
    const float* conv1_b = (const float*)d_in[4];
    const float* gn_g    = (const float*)d_in[5];
    const float* gn_b    = (const float*)d_in[6];
    const float* convh_w = (const float*)d_in[7];
    const float* convh_b = (const float*)d_in[8];
    const float* convw_w = (const float*)d_in[9];
    const float* convw_b = (const float*)d_in[10];
    float* out = (float*)d_out;

    cudaLaunchAttribute pdl[1];
    pdl[0].id = cudaLaunchAttributeProgrammaticStreamSerialization;
    pdl[0].val.programmaticStreamSerializationAllowed = 1;

    // K1a: x1 reductions (critical path head)
    k1a_kernel<<<dim3(CGH, BG), 256>>>(x);

    // K2: tiny conv/GN/conv chain, PDL on K1a
    cudaLaunchConfig_t cfg2 = {};
    cfg2.gridDim  = dim3(BG, 1, 1);
    cfg2.blockDim = dim3(256, 1, 1);
    cfg2.stream   = 0;
    cfg2.attrs    = pdl;
    cfg2.numAttrs = 1;
    cudaLaunchKernelEx(&cfg2, k2_kernel, conv1_w, conv1_b, gn_g, gn_b,
                       convh_w, convh_b, convw_w, convw_b);

    // K3: spatial gating, PDL on K2
    cudaLaunchConfig_t cfg3 = {};
    cfg3.gridDim  = dim3(CGH, BG, 1);
    cfg3.blockDim = dim3(256, 1, 1);
    cfg3.stream   = 0;
    cfg3.attrs    = pdl;
    cfg3.numAttrs = 1;
    cudaLaunchKernelEx(&cfg3, k3_kernel, x, out);

    // K1b: independent x0 stream, PDL so it backfills during K3; no grid-sync
    cudaLaunchConfig_t cfg1b = {};
    cfg1b.gridDim  = dim3(CGH, BG, 1);
    cfg1b.blockDim = dim3(256, 1, 1);
    cfg1b.stream   = 0;
    cfg1b.attrs    = pdl;
    cfg1b.numAttrs = 1;
    cudaLaunchKernelEx(&cfg1b, k1b_kernel, x, cweight, cbias, out);
}

// round 10
// speedup vs baseline: 2.2122x; 1.0524x over previous
#include <cuda_runtime.h>
#include <cstdint>

#define CTOT  512
#define BG    256      // N*G = 32*8 groups
#define CGH   32       // channels per half-group
#define PLANE 4096     // 64*64

__device__ __forceinline__ float sigmoid_exact(float z) {
    return __fdividef(1.0f, 1.0f + __expf(-z));
}
// 1-MUFU sigmoid: sigmoid(z) = 0.5*tanh(z/2) + 0.5
__device__ __forceinline__ float sigmoid_fast(float z) {
    float t;
    asm("tanh.approx.f32 %0, %1;" : "=f"(t) : "f"(z * 0.5f));
    return fmaf(0.5f, t, 0.5f);
}

// ---------------------------------------------------------------------------
// KS: whole spatial branch for one bg group per block.
//   1024 threads; warp w owns x1 plane w (32 planes).
//   Phase 1: read planes, row/col/total means -> smem
//   Phase 2: conv1 -> GroupNorm -> h-swish -> convh/convw (threads 0..255)
//   Phase 3: re-read planes (.cs, hot in L2), gate, write out (.cs)
// ---------------------------------------------------------------------------
__global__ __launch_bounds__(1024, 1) void ks_kernel(
    const float* __restrict__ x,
    const float* __restrict__ w1,  const float* __restrict__ b1,
    const float* __restrict__ gng, const float* __restrict__ gnb,
    const float* __restrict__ wh,  const float* __restrict__ bh,
    const float* __restrict__ wwv, const float* __restrict__ bw,
    float* __restrict__ out)
{
    cudaTriggerProgrammaticLaunchCompletion();   // let K1b start launching

    const int bg   = blockIdx.x;     // 0..255
    const int n    = bg >> 3;
    const int g    = bg & 7;
    const int t    = threadIdx.x;    // 0..1023
    const int wid  = t >> 5;         // plane index 0..31
    const int lane = t & 31;

    // smem: s_row/s_col double as s_ah/s_aw after conv1 consumes them
    __shared__ float s_row[32][64];      // x_h (row means)  -> later a_h
    __shared__ float s_col[32][64];      // x_w (col means)  -> later a_w
    __shared__ float s_xs[32];           // plane means
    __shared__ float ybuf[32][128];      // conv1 out / normalized
    __shared__ float w1s[1024], whs[1024], wws[1024];
    __shared__ float b1s[32], bhs[32], bws[32], gngs[32], gnbs[32];
    __shared__ float mus[32], rstds[32];

    // weights (independent of everything; issued first)
    w1s[t] = w1[t];
    whs[t] = wh[t];
    wws[t] = wwv[t];
    if (t < 32) {
        b1s[t] = b1[t]; bhs[t] = bh[t]; bws[t] = bw[t];
        gngs[t] = gng[t]; gnbs[t] = gnb[t];
    }

    // ---------------- phase 1: reductions (warp w = plane w) ----------------
    const float4* p4 = (const float4*)(x + (size_t)(n * CTOT + g * 64 + 32 + wid) * PLANE);
    // lane reads float4 j = lane + 32*i : row = (lane>>4) + 2*i, cols 4*(lane&15)..+3
    float4 colacc = make_float4(0.f, 0.f, 0.f, 0.f);
    #pragma unroll 8
    for (int i = 0; i < 32; i++) {
        float4 v = p4[lane + 32 * i];
        colacc.x += v.x; colacc.y += v.y; colacc.z += v.z; colacc.w += v.w;
        float s = v.x + v.y + v.z + v.w;
        s += __shfl_xor_sync(0xffffffffu, s, 8);
        s += __shfl_xor_sync(0xffffffffu, s, 4);
        s += __shfl_xor_sync(0xffffffffu, s, 2);
        s += __shfl_xor_sync(0xffffffffu, s, 1);
        if ((lane & 15) == 0)
            s_row[wid][2 * i + (lane >> 4)] = s * (1.0f / 64.0f);
    }
    // fold the two half-warps' row sets for columns
    colacc.x += __shfl_xor_sync(0xffffffffu, colacc.x, 16);
    colacc.y += __shfl_xor_sync(0xffffffffu, colacc.y, 16);
    colacc.z += __shfl_xor_sync(0xffffffffu, colacc.z, 16);
    colacc.w += __shfl_xor_sync(0xffffffffu, colacc.w, 16);
    if (lane < 16) {
        float4 cw;
        cw.x = colacc.x * (1.0f / 64.0f);
        cw.y = colacc.y * (1.0f / 64.0f);
        cw.z = colacc.z * (1.0f / 64.0f);
        cw.w = colacc.w * (1.0f / 64.0f);
        ((float4*)s_col[wid])[lane] = cw;
    }
    float cs = colacc.x + colacc.y + colacc.z + colacc.w;
    cs += __shfl_xor_sync(0xffffffffu, cs, 8);
    cs += __shfl_xor_sync(0xffffffffu, cs, 4);
    cs += __shfl_xor_sync(0xffffffffu, cs, 2);
    cs += __shfl_xor_sync(0xffffffffu, cs, 1);
    if (lane == 0) s_xs[wid] = cs * (1.0f / 4096.0f);
    __syncthreads();

    // ---------------- phase 2: conv1 -> GN -> h-swish -> convh/convw --------
    const int p  = t & 127;          // position 0..127
    const int oh = (t >> 7) * 16;    // only meaningful for t<256

    float a1[16];
    if (t < 256) {
        #pragma unroll
        for (int o = 0; o < 16; o++) a1[o] = b1s[oh + o];
        #pragma unroll
        for (int i = 0; i < 32; i++) {
            const float ci = (p < 64) ? s_row[i][p] : s_col[i][p - 64];
            #pragma unroll
            for (int o = 0; o < 16; o++)
                a1[o] += w1s[(oh + o) * 32 + i] * ci;
        }
    }
    __syncthreads();                 // s_row/s_col reads done -> reusable
    if (t < 256) {
        #pragma unroll
        for (int o = 0; o < 16; o++) ybuf[oh + o][p] = a1[o];
    }
    __syncthreads();

    if (t < 256) {                   // GN stats: warp w2 handles 4 channels
        const int w2 = t >> 5, l = t & 31;
        #pragma unroll
        for (int j = 0; j < 4; j++) {
            const int o = w2 * 4 + j;
            float e0 = ybuf[o][l],      e1 = ybuf[o][l + 32],
                  e2 = ybuf[o][l + 64], e3 = ybuf[o][l + 96];
            float s  = e0 + e1 + e2 + e3;
            float ss = e0 * e0 + e1 * e1 + e2 * e2 + e3 * e3;
            #pragma unroll
            for (int off = 16; off > 0; off >>= 1) {
                s  += __shfl_xor_sync(0xffffffffu, s, off);
                ss += __shfl_xor_sync(0xffffffffu, ss, off);
            }
            if (l == 0) {
                float mu  = s * (1.0f / 128.0f);
                float var = ss * (1.0f / 128.0f) - mu * mu;
                mus[o]   = mu;
                rstds[o] = rsqrtf(var + 1e-5f);
            }
        }
    }
    __syncthreads();

    if (t < 256) {                   // normalize + affine + h-swish
        #pragma unroll
        for (int j = 0; j < 16; j++) {
            const int k = oh + j;
            float v = (ybuf[k][p] - mus[k]) * rstds[k] * gngs[k] + gnbs[k];
            float hs = fminf(fmaxf(v + 3.0f, 0.0f), 6.0f) * (1.0f / 6.0f);
            ybuf[k][p] = v * hs;
        }
    }
    __syncthreads();

    if (t < 256) {                   // convh (p<64) -> s_row, convw -> s_col
        const int half = p >> 6;
        const int r    = p & 63;
        const float* wsel = half ? wws : whs;
        const float* bsel = half ? bws : bhs;
        float a2[16];
        #pragma unroll
        for (int o = 0; o < 16; o++) a2[o] = bsel[oh + o];
        #pragma unroll
        for (int i = 0; i < 32; i++) {
            const float ci = ybuf[i][p];
            #pragma unroll
            for (int o = 0; o < 16; o++)
                a2[o] += wsel[(oh + o) * 32 + i] * ci;
        }
        if (half) {
            #pragma unroll
            for (int o = 0; o < 16; o++) s_col[oh + o][r] = a2[o];   // a_w
        } else {
            #pragma unroll
            for (int o = 0; o < 16; o++) s_row[oh + o][r] = a2[o];   // a_h
        }
    }
    __syncthreads();

    // ---------------- phase 3: gate + write (warp w = plane w) --------------
    const float xs = s_xs[wid];
    float4 aw4 = ((float4*)s_col[wid])[lane & 15];
    aw4.x *= xs; aw4.y *= xs; aw4.z *= xs; aw4.w *= xs;

    const int c_prev  = g * 64 + 32 + wid;
    const int c_final = 2 * (c_prev & 255) + (c_prev >> 8);
    float4* o4 = (float4*)(out + (size_t)(n * CTOT + c_final) * PLANE);

    #pragma unroll 8
    for (int i = 0; i < 32; i++) {
        float4 v = __ldcs(&p4[lane + 32 * i]);            // hot in L2
        const float ah = s_row[wid][2 * i + (lane >> 4)];
        v.x *= sigmoid_fast(ah * aw4.x);
        v.y *= sigmoid_fast(ah * aw4.y);
        v.z *= sigmoid_fast(ah * aw4.z);
        v.w *= sigmoid_fast(ah * aw4.w);
        __stcs(&o4[lane + 32 * i], v);
    }
}

// ---------------------------------------------------------------------------
// K1b: x0 channel-gating stream. Independent; PDL so it backfills during KS.
// ---------------------------------------------------------------------------
__global__ __launch_bounds__(256) void k1b_kernel(
    const float* __restrict__ x,
    const float* __restrict__ cweight,
    const float* __restrict__ cbias,
    float* __restrict__ out)
{
    const int cc = blockIdx.x;          // 0..31
    const int bg = blockIdx.y;          // 0..255
    const int n  = bg >> 3;
    const int g  = bg & 7;
    const int t  = threadIdx.x;

    const float4* p4 = (const float4*)(x + (size_t)(n * CTOT + g * 64 + cc) * PLANE);
    float4 v[4];
    #pragma unroll
    for (int i = 0; i < 4; i++) v[i] = __ldcs(&p4[t + 256 * i]);

    float s = 0.f;
    #pragma unroll
    for (int i = 0; i < 4; i++) s += v[i].x + v[i].y + v[i].z + v[i].w;
    __shared__ float ws[8];
    __shared__ float sgate;
    #pragma unroll
    for (int o = 16; o > 0; o >>= 1) s += __shfl_xor_sync(0xffffffffu, s, o);
    if ((t & 31) == 0) ws[t >> 5] = s;
    __syncthreads();
    if (t == 0) {
        float tot = 0.f;
        #pragma unroll
        for (int i = 0; i < 8; i++) tot += ws[i];
        float gap = tot * (1.0f / 4096.0f);
        sgate = sigmoid_exact(cweight[cc] * gap + cbias[cc]);
    }
    __syncthreads();
    const float gate = sgate;

    const int c_prev  = g * 64 + cc;
    const int c_final = 2 * (c_prev & 255) + (c_prev >> 8);
    float4* o4 = (float4*)(out + (size_t)(n * CTOT + c_final) * PLANE);
    #pragma unroll
    for (int i = 0; i < 4; i++) {
        float4 r = v[i];
        r.x *= gate; r.y *= gate; r.z *= gate; r.w *= gate;
        __stcs(&o4[t + 256 * i], r);
    }
}

// ---------------------------------------------------------------------------
extern "C" void kernel_launch(void* const* d_in, const int* in_sizes, int n_in,
                              void* d_out, int out_size)
{
    const float* x       = (const float*)d_in[0];
    const float* cweight = (const float*)d_in[1];
    const float* cbias   = (const float*)d_in[2];
    const float* conv1_w = (const float*)d_in[3];
    const float* conv1_b = (const float*)d_in[4];
    const float* gn_g    = (const float*)d_in[5];
    const float* gn_b    = (const float*)d_in[6];
    const float* convh_w = (const float*)d_in[7];
    const float* convh_b = (const float*)d_in[8];
    const float* convw_w = (const float*)d_in[9];
    const float* convw_b = (const float*)d_in[10];
    float* out = (float*)d_out;

    // spatial branch: 256 bg-monolithic blocks
    ks_kernel<<<BG, 1024>>>(x, conv1_w, conv1_b, gn_g, gn_b,
                            convh_w, convh_b, convw_w, convw_b, out);

    // channel branch: independent, PDL backfill
    cudaLaunchAttribute pdl[1];
    pdl[0].id = cudaLaunchAttributeProgrammaticStreamSerialization;
    pdl[0].val.programmaticStreamSerializationAllowed = 1;

    cudaLaunchConfig_t cfg = {};
    cfg.gridDim  = dim3(CGH, BG, 1);
    cfg.blockDim = dim3(256, 1, 1);
    cfg.stream   = 0;
    cfg.attrs    = pdl;
    cfg.numAttrs = 1;
    cudaLaunchKernelEx(&cfg, k1b_kernel, x, cweight, cbias, out);
}